// round 11
// baseline (speedup 1.0000x reference)
#include <cuda_runtime.h>
#include <cuda_bf16.h>
#include <cuda_fp16.h>
#include <math.h>
#include <cstdint>

#define N 4096
#define D 256
#define NB (N / 128)
#define NTILES (NB * (NB + 1) / 2)   // 528
#define NLAB 512
#define GCTAS 148
#define GEMM_CTAS 147

// ---------------- device globals ----------------
__device__ __align__(16) __nv_bfloat16  g_normh[N * D]; // rows pre-swizzled: chunk c at c^(row&7)
__device__ int      g_lab[N];
__device__ float    g_tot[N];
__device__ float    g_loss_f;
__device__ int      g_bstart[NLAB + 1];
__device__ int      g_bidx[N];
__device__ unsigned g_npair;
__device__ unsigned g_bar;
__device__ unsigned g_gen;

// ---------------- smem layout ----------------
#define SMEM_A0   0
#define SMEM_A1   65536
#define SMEM_B    131072
#define SMEM_MBA0 196608
#define SMEM_MBA1 196616
#define SMEM_MBB  196624
#define SMEM_GT   196736
// phase-2 per-warp slice (reuses GEMM smem): 9216 B each, 16 warps = 147456
#define P2_SLICE  9216
#define P2_SMAX   16        // fast-path bucket capacity (rows cached in smem)

__device__ __forceinline__ uint32_t smem_u32(const void* p) {
    uint32_t a;
    asm("{ .reg .u64 t; cvta.to.shared.u64 t, %1; cvt.u32.u64 %0, t; }" : "=r"(a) : "l"(p));
    return a;
}
#define MBAR_INIT(mb, c)  asm volatile("mbarrier.init.shared.b64 [%0], %1;" :: "r"(mb), "r"(c) : "memory")
#define MBAR_EXPECT(mb, tx) asm volatile("mbarrier.arrive.expect_tx.shared.b64 _, [%0], %1;" :: "r"(mb), "r"(tx) : "memory")
#define BULK_LD(dst, src, sz, mb) \
    asm volatile("cp.async.bulk.shared::cta.global.mbarrier::complete_tx::bytes [%0], [%1], %2, [%3];" \
        :: "r"(dst), "l"(src), "r"(sz), "r"(mb) : "memory")

__device__ __forceinline__ void mbar_wait(uint32_t mb, uint32_t parity) {
    uint32_t done;
    asm volatile("{ .reg .pred p; mbarrier.try_wait.parity.acquire.cta.shared::cta.b64 p, [%1], %2; selp.b32 %0, 1, 0, p; }"
                 : "=r"(done) : "r"(mb), "r"(parity) : "memory");
    if (!done) {
        asm volatile("{ .reg .pred P1; W%=: mbarrier.try_wait.parity.acquire.cta.shared::cta.b64 P1, [%0], %1, 0x989680; @P1 bra.uni DN%=; bra.uni W%=; DN%=: }"
                     :: "r"(mb), "r"(parity) : "memory");
    }
}

#define LDSM4(r, a) \
    asm volatile("ldmatrix.sync.aligned.m8n8.x4.shared.b16 {%0,%1,%2,%3}, [%4];" \
        : "=r"((r)[0]), "=r"((r)[1]), "=r"((r)[2]), "=r"((r)[3]) : "r"(a))
#define LDSM4T(r, a) \
    asm volatile("ldmatrix.sync.aligned.m8n8.x4.trans.shared.b16 {%0,%1,%2,%3}, [%4];" \
        : "=r"((r)[0]), "=r"((r)[1]), "=r"((r)[2]), "=r"((r)[3]) : "r"(a))
#define MMA16816(d, a, b0_, b1_) \
    asm volatile("mma.sync.aligned.m16n8k16.row.col.f32.bf16.bf16.f32 " \
        "{%0,%1,%2,%3}, {%4,%5,%6,%7}, {%8,%9}, {%0,%1,%2,%3};" \
        : "+f"((d)[0]), "+f"((d)[1]), "+f"((d)[2]), "+f"((d)[3]) \
        : "r"((a)[0]), "r"((a)[1]), "r"((a)[2]), "r"((a)[3]), "r"(b0_), "r"(b1_))

__device__ __forceinline__ void grid_barrier(int tid) {
    __syncthreads();
    if (tid == 0) {
        __threadfence();
        unsigned gen = *(volatile unsigned*)&g_gen;
        unsigned t = atomicAdd(&g_bar, 1u);
        if (t == GCTAS - 1) {
            *(volatile unsigned*)&g_bar = 0u;
            __threadfence();
            atomicAdd(&g_gen, 1u);
        } else {
            while (*(volatile unsigned*)&g_gen == gen) __nanosleep(32);
        }
        __threadfence();
    }
    __syncthreads();
}

__device__ __forceinline__ void tile_decode(int t, int& bi, int& bj) {
    int b = (int)((sqrtf(8.f * (float)t + 1.f) - 1.f) * 0.5f);
    while ((b + 1) * (b + 2) / 2 <= t) b++;
    while (b * (b + 1) / 2 > t) b--;
    bj = b;
    bi = t - b * (b + 1) / 2;
}

__device__ __forceinline__ void tri_decode(int p, int n, int& a, int& b) {
    a = 0;
    int rem = p;
    while (rem >= n - 1 - a) { rem -= (n - 1 - a); a++; }
    b = a + 1 + rem;
}

__device__ __forceinline__ float dot_u4(uint4 xa, uint4 xb, float s) {
    const uint32_t* qa = (const uint32_t*)&xa;
    const uint32_t* qb = (const uint32_t*)&xb;
    #pragma unroll
    for (int q = 0; q < 4; q++) {
        float2 fa = __bfloat1622float2(*(const __nv_bfloat162*)&qa[q]);
        float2 fb = __bfloat1622float2(*(const __nv_bfloat162*)&qb[q]);
        s += fa.x * fb.x + fa.y * fb.y;
    }
    return s;
}

// =====================================================================
// ONE persistent kernel, all phases wide.
// =====================================================================
__global__ __launch_bounds__(512, 1) void k_all(const float* __restrict__ x,
                                                const void* __restrict__ labels,
                                                float* __restrict__ out) {
    extern __shared__ char smem[];
    const int tid = threadIdx.x, wid = tid >> 5, l = tid & 31;
    const int wm = wid & 3, wn = wid >> 2;
    const uint32_t sb = smem_u32(smem);
    const int cta = blockIdx.x;

    if (tid == 0) {
        MBAR_INIT(sb + SMEM_MBA0, 1);
        MBAR_INIT(sb + SMEM_MBA1, 1);
        MBAR_INIT(sb + SMEM_MBB, 1);
        if (cta == 0) g_loss_f = 0.f;
    }

    // ---------------- Phase 0: warp-per-row normalize ----------------
    {
        const int gw = cta * 16 + wid;
        for (int row = gw; row < N; row += GCTAS * 16) {
            float4 v0 = *(const float4*)&x[row * D + l * 8];
            float4 v1 = *(const float4*)&x[row * D + l * 8 + 4];
            float sq = v0.x * v0.x + v0.y * v0.y + v0.z * v0.z + v0.w * v0.w
                     + v1.x * v1.x + v1.y * v1.y + v1.z * v1.z + v1.w * v1.w;
            #pragma unroll
            for (int o = 16; o > 0; o >>= 1) sq += __shfl_xor_sync(0xffffffffu, sq, o);
            float inv = 1.0f / fmaxf(sqrtf(sq), 1e-12f);
            __nv_bfloat162 h0 = __floats2bfloat162_rn(v0.x * inv, v0.y * inv);
            __nv_bfloat162 h1 = __floats2bfloat162_rn(v0.z * inv, v0.w * inv);
            __nv_bfloat162 h2 = __floats2bfloat162_rn(v1.x * inv, v1.y * inv);
            __nv_bfloat162 h3 = __floats2bfloat162_rn(v1.z * inv, v1.w * inv);
            uint4 pk;
            pk.x = *(uint32_t*)&h0; pk.y = *(uint32_t*)&h1;
            pk.z = *(uint32_t*)&h2; pk.w = *(uint32_t*)&h3;
            int cs = l ^ (row & 7);
            *(uint4*)&g_normh[row * D + cs * 8] = pk;
            if (l == 0) g_tot[row] = 0.f;
        }
    }

    grid_barrier(tid);

    // ---------------- Phase 1: GEMM (CTAs 0..146) | bucket (CTA 147) ----------------
    if (cta == GEMM_CTAS) {
        // Bucket: sniff + histogram + scans + scatter. smem scratch in GEMM area.
        int* cnt  = (int*)smem;
        int* bufA = cnt + NLAB;
        int* bufB = bufA + NLAB;
        int* s_nz = bufB + NLAB;
        int* s_np = s_nz + 1;
        if (tid == 0) { *s_nz = 0; *s_np = 0; }
        cnt[tid] = 0;
        __syncthreads();
        const int* l32 = (const int*)labels;
        int nz = 0;
        #pragma unroll
        for (int i = tid; i < N / 2; i += NLAB) nz |= (l32[2 * i + 1] != 0);
        if (nz) atomicOr(s_nz, 1);
        __syncthreads();
        const bool is64 = (*s_nz == 0);
        #pragma unroll
        for (int r = tid; r < N; r += NLAB) {
            int lv = is64 ? (int)((const long long*)labels)[r] : l32[r];
            g_lab[r] = lv;
            atomicAdd(&cnt[lv], 1);
        }
        __syncthreads();
        const int n_t = cnt[tid];
        atomicAdd(s_np, n_t * (n_t - 1) / 2);
        bufA[tid] = n_t;
        __syncthreads();
        int* sc = bufA; int* dst = bufB;
        #pragma unroll
        for (int o = 1; o < NLAB; o <<= 1) {
            int v = sc[tid];
            if (tid >= o) v += sc[tid - o];
            dst[tid] = v;
            int* tmp = sc; sc = dst; dst = tmp;
            __syncthreads();
        }
        const int row_excl = sc[tid] - n_t;
        g_bstart[tid] = row_excl;
        if (tid == NLAB - 1) g_bstart[NLAB] = N;
        cnt[tid] = row_excl;
        __syncthreads();
        #pragma unroll
        for (int r = tid; r < N; r += NLAB) {
            int p = atomicAdd(&cnt[g_lab[r]], 1);
            g_bidx[p] = r;
        }
        __syncthreads();
        if (tid == 0) g_npair = (unsigned)*s_np;
    } else {
        const int s = (int)(((long)cta * NTILES) / GEMM_CTAS);
        const int e = (int)(((long)(cta + 1) * NTILES) / GEMM_CTAS);

        int aph[2] = {0, 0}, bph = 0;
        int ab = 0;
        bool a_issued = false;
        int prev_bj = -1;
        const half2 SC = __float2half2_rn(2.8853900817779268f);   // 2*log2(e)

        for (int t = s; t < e; t++) {
            int bi, bj;
            tile_decode(t, bi, bj);
            const bool diag = (bi == bj);
            const bool newcol = (bj != prev_bj);
            prev_bj = bj;
            const int iBase = bi * 128;
            const int jBase = bj * 128;

            __syncthreads();

            if (tid == 0) {
                if (newcol) {
                    MBAR_EXPECT(sb + SMEM_MBB, 65536u);
                    #pragma unroll
                    for (int q = 0; q < 8; q++)
                        BULK_LD(sb + SMEM_B + q * 8192,
                                (const char*)&g_normh[(size_t)jBase * D] + q * 8192, 8192u, sb + SMEM_MBB);
                }
                if (!diag && !a_issued) {
                    uint32_t mba = sb + (ab ? SMEM_MBA1 : SMEM_MBA0);
                    uint32_t abuf = (ab ? SMEM_A1 : SMEM_A0);
                    MBAR_EXPECT(mba, 65536u);
                    #pragma unroll
                    for (int q = 0; q < 8; q++)
                        BULK_LD(sb + abuf + q * 8192,
                                (const char*)&g_normh[(size_t)iBase * D] + q * 8192, 8192u, mba);
                }
            }

            if (newcol) { mbar_wait(sb + SMEM_MBB, bph); bph ^= 1; }
            if (!diag)  { mbar_wait(sb + (ab ? SMEM_MBA1 : SMEM_MBA0), aph[ab]); aph[ab] ^= 1; }
            __syncthreads();

            float acc[2][4][4];
            #pragma unroll
            for (int mt = 0; mt < 2; mt++)
                #pragma unroll
                for (int nt = 0; nt < 4; nt++)
                    #pragma unroll
                    for (int ee = 0; ee < 4; ee++) acc[mt][nt][ee] = 0.f;

            const uint32_t aspace = diag ? (uint32_t)SMEM_B : (ab ? (uint32_t)SMEM_A1 : (uint32_t)SMEM_A0);
            const int row_a = wm * 32 + (l & 15);
            const uint32_t abase = sb + aspace + (uint32_t)row_a * 512;
            const int rxa = row_a & 7;
            const int hia = (l >> 4);
            const int row_b = wn * 32 + (l & 7) + ((l & 16) ? 8 : 0);
            const uint32_t bbase = sb + SMEM_B + (uint32_t)row_b * 512;
            const int rxb = row_b & 7;
            const int hib = (l >> 3) & 1;

            #pragma unroll
            for (int ks = 0; ks < 16; ks++) {
                const uint32_t ka = (uint32_t)(((ks * 2 + hia) ^ rxa) << 4);
                const uint32_t kb = (uint32_t)(((ks * 2 + hib) ^ rxb) << 4);
                uint32_t A0[4], A1[4];
                LDSM4(A0, abase + ka);
                LDSM4(A1, abase + 8192 + ka);
                #pragma unroll
                for (int p = 0; p < 2; p++) {
                    uint32_t Bt[4];
                    LDSM4T(Bt, bbase + (uint32_t)p * 8192 + kb);
                    MMA16816(acc[0][2 * p],     A0, Bt[0], Bt[1]);
                    MMA16816(acc[0][2 * p + 1], A0, Bt[2], Bt[3]);
                    MMA16816(acc[1][2 * p],     A1, Bt[0], Bt[1]);
                    MMA16816(acc[1][2 * p + 1], A1, Bt[2], Bt[3]);
                }
            }
            __syncthreads();

            a_issued = false;
            if (t + 1 < e) {
                int bi2, bj2;
                tile_decode(t + 1, bi2, bj2);
                if (bi2 != bj2) {
                    const int nb = diag ? ab : (ab ^ 1);
                    if (tid == 0) {
                        uint32_t mba = sb + (nb ? SMEM_MBA1 : SMEM_MBA0);
                        uint32_t abuf = (nb ? SMEM_A1 : SMEM_A0);
                        MBAR_EXPECT(mba, 65536u);
                        #pragma unroll
                        for (int q = 0; q < 8; q++)
                            BULK_LD(sb + abuf + q * 8192,
                                    (const char*)&g_normh[(size_t)(bi2 * 128) * D] + q * 8192, 8192u, mba);
                    }
                    ab = nb;
                    a_issued = true;
                }
            }

            half2 ctot2[4];
            #pragma unroll
            for (int nt = 0; nt < 4; nt++) ctot2[nt] = __float2half2_rn(0.f);
            half2 cidx[4];
            if (diag) {
                #pragma unroll
                for (int nt = 0; nt < 4; nt++) {
                    float c0 = (float)(wn * 32 + nt * 8 + (l & 3) * 2);
                    cidx[nt] = __floats2half2_rn(c0, c0 + 1.0f);
                }
            }
            #pragma unroll
            for (int mt = 0; mt < 2; mt++) {
                #pragma unroll
                for (int half_ = 0; half_ < 2; half_++) {
                    const int row_local = wm * 32 + mt * 16 + half_ * 8 + (l >> 2);
                    const int gi = iBase + row_local;
                    half2 t2 = __float2half2_rn(0.f);
                    if (diag) {
                        const half2 r2 = __float2half2_rn((float)row_local);
                        #pragma unroll
                        for (int nt = 0; nt < 4; nt++) {
                            half2 h = __floats2half2_rn(acc[mt][nt][half_ * 2], acc[mt][nt][half_ * 2 + 1]);
                            half2 ex = h2exp2(__hmul2(h, SC));
                            half2 eq = __heq2(cidx[nt], r2);
                            ex = __hsub2(ex, __hmul2(ex, eq));
                            t2 = __hadd2(t2, ex);
                            ctot2[nt] = __hadd2(ctot2[nt], ex);
                        }
                    } else {
                        #pragma unroll
                        for (int nt = 0; nt < 4; nt++) {
                            half2 h = __floats2half2_rn(acc[mt][nt][half_ * 2], acc[mt][nt][half_ * 2 + 1]);
                            half2 ex = h2exp2(__hmul2(h, SC));
                            t2 = __hadd2(t2, ex);
                            ctot2[nt] = __hadd2(ctot2[nt], ex);
                        }
                    }
                    float2 f = __half22float2(t2);
                    float tt = f.x + f.y;
                    tt += __shfl_xor_sync(0xffffffffu, tt, 1);
                    tt += __shfl_xor_sync(0xffffffffu, tt, 2);
                    if ((l & 3) == 0) atomicAdd(&g_tot[gi], tt);
                }
            }
            if (!diag) {
                #pragma unroll
                for (int nt = 0; nt < 4; nt++) {
                    uint32_t v = *(uint32_t*)&ctot2[nt];
                    #pragma unroll
                    for (int m = 4; m <= 16; m <<= 1) {
                        uint32_t o = __shfl_xor_sync(0xffffffffu, v, m);
                        half2 hv = *(half2*)&v, ho = *(half2*)&o;
                        hv = __hadd2(hv, ho);
                        v = *(uint32_t*)&hv;
                    }
                    if (l < 4) {
                        float2 fc = __half22float2(*(half2*)&v);
                        int c0 = wn * 32 + nt * 8 + l * 2;
                        atomicAdd(&g_tot[jBase + c0], fc.x);
                        atomicAdd(&g_tot[jBase + c0 + 1], fc.y);
                    }
                }
            }
        }
    }

    grid_barrier(tid);

    // ---------------- Phase 2: warp-per-bucket loss ----------------
    {
        char* slice = smem + wid * P2_SLICE;
        uint4* rows = (uint4*)slice;               // [16][32]
        float* ssc  = (float*)(slice + 8192);      // s scratch (<=120)
        float* pos  = (float*)(slice + 8704);      // [16]
        float* neg  = (float*)(slice + 8768);      // [16]
        float lsum = 0.f;
        const int gw = cta * 16 + wid;

        for (int L = gw; L < NLAB; L += GCTAS * 16) {
            const int base = g_bstart[L];
            const int n = g_bstart[L + 1] - base;
            if (n < 2) continue;
            const int np = n * (n - 1) / 2;

            if (n <= P2_SMAX) {
                int myrow = g_bidx[base + (l < n ? l : 0)];
                // stage rows: chunk idx over n*32
                for (int idx = l; idx < n * 32; idx += 32) {
                    int r = idx >> 5, c = idx & 31;
                    int gr = __shfl_sync(0xffffffffu, myrow, r);
                    rows[r * 32 + (c ^ (r & 7))] =
                        *(const uint4*)&g_normh[(size_t)gr * D + (size_t)((c ^ (gr & 7)) * 8)];
                }
                if (l < n) pos[l] = 0.f;
                __syncwarp();
                // pass 1: thread-per-pair dots -> s scratch + pos
                for (int p = l; p < np; p += 32) {
                    int a, b;
                    tri_decode(p, n, a, b);
                    float s = 0.f;
                    #pragma unroll 8
                    for (int k = 0; k < 32; k++)
                        s = dot_u4(rows[a * 32 + (k ^ (a & 7))], rows[b * 32 + (k ^ (b & 7))], s);
                    ssc[p] = s;
                    float e = __expf(2.0f * s);
                    atomicAdd(&pos[a], e);
                    atomicAdd(&pos[b], e);
                }
                __syncwarp();
                if (l < n) neg[l] = g_tot[myrow] - pos[l];
                __syncwarp();
                // pass 2: loss
                for (int p = l; p < np; p += 32) {
                    int a, b;
                    tri_decode(p, n, a, b);
                    float s = ssc[p];
                    float e = __expf(2.0f * s);
                    lsum += logf(e + neg[a]) + logf(e + neg[b]) - 4.0f * s;
                }
                __syncwarp();
            } else {
                // medium path: rows from gmem, s recomputed (rare)
                float* posM = (float*)slice;            // [n]
                float* negM = (float*)(slice + 4096);   // [n]
                for (int r = l; r < n; r += 32) posM[r] = 0.f;
                __syncwarp();
                for (int p = l; p < np; p += 32) {
                    int a, b;
                    tri_decode(p, n, a, b);
                    int ga = g_bidx[base + a], gb = g_bidx[base + b];
                    float s = 0.f;
                    for (int k = 0; k < 32; k++)
                        s = dot_u4(*(const uint4*)&g_normh[(size_t)ga * D + (size_t)((k ^ (ga & 7)) * 8)],
                                   *(const uint4*)&g_normh[(size_t)gb * D + (size_t)((k ^ (gb & 7)) * 8)], s);
                    float e = __expf(2.0f * s);
                    atomicAdd(&posM[a], e);
                    atomicAdd(&posM[b], e);
                }
                __syncwarp();
                for (int r = l; r < n; r += 32) negM[r] = g_tot[g_bidx[base + r]] - posM[r];
                __syncwarp();
                for (int p = l; p < np; p += 32) {
                    int a, b;
                    tri_decode(p, n, a, b);
                    int ga = g_bidx[base + a], gb = g_bidx[base + b];
                    float s = 0.f;
                    for (int k = 0; k < 32; k++)
                        s = dot_u4(*(const uint4*)&g_normh[(size_t)ga * D + (size_t)((k ^ (ga & 7)) * 8)],
                                   *(const uint4*)&g_normh[(size_t)gb * D + (size_t)((k ^ (gb & 7)) * 8)], s);
                    float e = __expf(2.0f * s);
                    lsum += logf(e + negM[a]) + logf(e + negM[b]) - 4.0f * s;
                }
                __syncwarp();
            }
        }
        #pragma unroll
        for (int o = 16; o > 0; o >>= 1) lsum += __shfl_down_sync(0xffffffffu, lsum, o);
        if (l == 0 && lsum != 0.f) atomicAdd(&g_loss_f, lsum);
    }

    grid_barrier(tid);

    if (cta == 0 && tid == 0)
        out[0] = g_loss_f / (float)(2u * g_npair);
}

// ---------------- launch ----------------
extern "C" void kernel_launch(void* const* d_in, const int* in_sizes, int n_in,
                              void* d_out, int out_size) {
    const float* x = (const float*)d_in[0];
    const void* labels = d_in[1];

    static bool attr_done = false;
    if (!attr_done) {
        cudaFuncSetAttribute(k_all, cudaFuncAttributeMaxDynamicSharedMemorySize, SMEM_GT);
        attr_done = true;
    }

    k_all<<<GCTAS, 512, SMEM_GT>>>(x, labels, (float*)d_out);
}

// round 12
// speedup vs baseline: 1.6463x; 1.6463x over previous
#include <cuda_runtime.h>
#include <cuda_bf16.h>
#include <cuda_fp16.h>
#include <math.h>
#include <cstdint>

#define N 4096
#define D 256
#define NB (N / 128)
#define NTILES (NB * (NB + 1) / 2)   // 528
#define GCTAS 148
#define PAIR_CAP (1u << 23)
#define PBUF_CAP 192u

// ---------------- device globals ----------------
__device__ __align__(16) __nv_bfloat16  g_normh[N * D]; // rows pre-swizzled: chunk c at c^(row&7)
__device__ __align__(16) __half         g_labh[N];      // labels as half (exact, <2048)
__device__ float    g_neg[N];
__device__ float    g_loss_f;
__device__ unsigned g_npair;
__device__ unsigned g_done;
__device__ unsigned g_pair_ij[PAIR_CAP];
__device__ float    g_pair_s[PAIR_CAP];

// ---------------- smem layout ----------------
#define SMEM_A0   0
#define SMEM_A1   65536
#define SMEM_B    131072
#define SMEM_MBA0 196608
#define SMEM_MBA1 196616
#define SMEM_MBB  196624
#define SMEM_LABI 196640
#define SMEM_LABJ 196896
#define SMEM_PCNT 197152
#define SMEM_PIJ  197168
#define SMEM_PS   (197168 + PBUF_CAP * 4)
#define SMEM_GT   (SMEM_PS + PBUF_CAP * 4)

__device__ __forceinline__ uint32_t smem_u32(const void* p) {
    uint32_t a;
    asm("{ .reg .u64 t; cvta.to.shared.u64 t, %1; cvt.u32.u64 %0, t; }" : "=r"(a) : "l"(p));
    return a;
}
#define MBAR_INIT(mb, c)  asm volatile("mbarrier.init.shared.b64 [%0], %1;" :: "r"(mb), "r"(c) : "memory")
#define MBAR_EXPECT(mb, tx) asm volatile("mbarrier.arrive.expect_tx.shared.b64 _, [%0], %1;" :: "r"(mb), "r"(tx) : "memory")
#define BULK_LD(dst, src, sz, mb) \
    asm volatile("cp.async.bulk.shared::cta.global.mbarrier::complete_tx::bytes [%0], [%1], %2, [%3];" \
        :: "r"(dst), "l"(src), "r"(sz), "r"(mb) : "memory")

__device__ __forceinline__ void mbar_wait(uint32_t mb, uint32_t parity) {
    uint32_t done;
    asm volatile("{ .reg .pred p; mbarrier.try_wait.parity.acquire.cta.shared::cta.b64 p, [%1], %2; selp.b32 %0, 1, 0, p; }"
                 : "=r"(done) : "r"(mb), "r"(parity) : "memory");
    if (!done) {
        asm volatile("{ .reg .pred P1; W%=: mbarrier.try_wait.parity.acquire.cta.shared::cta.b64 P1, [%0], %1, 0x989680; @P1 bra.uni DN%=; bra.uni W%=; DN%=: }"
                     :: "r"(mb), "r"(parity) : "memory");
    }
}

#define LDSM4(r, a) \
    asm volatile("ldmatrix.sync.aligned.m8n8.x4.shared.b16 {%0,%1,%2,%3}, [%4];" \
        : "=r"((r)[0]), "=r"((r)[1]), "=r"((r)[2]), "=r"((r)[3]) : "r"(a))
#define LDSM4T(r, a) \
    asm volatile("ldmatrix.sync.aligned.m8n8.x4.trans.shared.b16 {%0,%1,%2,%3}, [%4];" \
        : "=r"((r)[0]), "=r"((r)[1]), "=r"((r)[2]), "=r"((r)[3]) : "r"(a))
#define MMA16816(d, a, b0_, b1_) \
    asm volatile("mma.sync.aligned.m16n8k16.row.col.f32.bf16.bf16.f32 " \
        "{%0,%1,%2,%3}, {%4,%5,%6,%7}, {%8,%9}, {%0,%1,%2,%3};" \
        : "+f"((d)[0]), "+f"((d)[1]), "+f"((d)[2]), "+f"((d)[3]) \
        : "r"((a)[0]), "r"((a)[1]), "r"((a)[2]), "r"((a)[3]), "r"(b0_), "r"(b1_))

__device__ __forceinline__ void tile_decode(int t, int& bi, int& bj) {
    int b = (int)((sqrtf(8.f * (float)t + 1.f) - 1.f) * 0.5f);
    while ((b + 1) * (b + 2) / 2 <= t) b++;
    while (b * (b + 1) / 2 > t) b--;
    bj = b;
    bi = t - b * (b + 1) / 2;
}

// ---------------- kernels ----------------
// Warp-per-row normalize + label convert + counter resets.
__global__ __launch_bounds__(256) void k_norm(const float* __restrict__ x,
                                              const void* __restrict__ labels) {
    __shared__ int s_nz;
    const int tid = threadIdx.x, wid = tid >> 5, l = tid & 31;
    if (tid == 0) {
        s_nz = 0;
        if (blockIdx.x == 0) { g_npair = 0u; g_done = 0u; g_loss_f = 0.f; }
    }
    __syncthreads();
    const int* l32 = (const int*)labels;
    if (tid < 128 && l32[2 * tid + 1] != 0) atomicOr(&s_nz, 1);
    __syncthreads();
    const bool is64 = (s_nz == 0);

    for (int row = blockIdx.x * 8 + wid; row < N; row += 2048) {
        float4 v0 = *(const float4*)&x[row * D + l * 8];
        float4 v1 = *(const float4*)&x[row * D + l * 8 + 4];
        float sq = v0.x * v0.x + v0.y * v0.y + v0.z * v0.z + v0.w * v0.w
                 + v1.x * v1.x + v1.y * v1.y + v1.z * v1.z + v1.w * v1.w;
        #pragma unroll
        for (int o = 16; o > 0; o >>= 1) sq += __shfl_xor_sync(0xffffffffu, sq, o);
        float inv = 1.0f / fmaxf(sqrtf(sq), 1e-12f);
        __nv_bfloat162 h0 = __floats2bfloat162_rn(v0.x * inv, v0.y * inv);
        __nv_bfloat162 h1 = __floats2bfloat162_rn(v0.z * inv, v0.w * inv);
        __nv_bfloat162 h2 = __floats2bfloat162_rn(v1.x * inv, v1.y * inv);
        __nv_bfloat162 h3 = __floats2bfloat162_rn(v1.z * inv, v1.w * inv);
        uint4 pk;
        pk.x = *(uint32_t*)&h0; pk.y = *(uint32_t*)&h1;
        pk.z = *(uint32_t*)&h2; pk.w = *(uint32_t*)&h3;
        int cs = l ^ (row & 7);
        *(uint4*)&g_normh[row * D + cs * 8] = pk;
        if (l == 0) {
            int lv = is64 ? (int)((const long long*)labels)[row] : l32[row];
            g_labh[row] = __float2half((float)lv);
            g_neg[row] = 0.f;
        }
    }
}

// Persistent bf16 mma.sync GEMM over upper-triangle tiles.
// Epilogue: neg sums (label-match masked out) + (i,j,s) pair emission via smem buffer.
__global__ __launch_bounds__(512, 1) void k_gemm() {
    extern __shared__ char smem[];
    const int tid = threadIdx.x, wid = tid >> 5, l = tid & 31;
    const int wm = wid & 3, wn = wid >> 2;
    const uint32_t sb = smem_u32(smem);
    const __half* labih = (const __half*)(smem + SMEM_LABI);
    const half2* labjh2 = (const half2*)(smem + SMEM_LABJ);
    unsigned* scnt = (unsigned*)(smem + SMEM_PCNT);
    unsigned* spij = (unsigned*)(smem + SMEM_PIJ);
    float*    sps  = (float*)(smem + SMEM_PS);

    if (tid == 0) {
        MBAR_INIT(sb + SMEM_MBA0, 1);
        MBAR_INIT(sb + SMEM_MBA1, 1);
        MBAR_INIT(sb + SMEM_MBB, 1);
        scnt[0] = 0;
    }
    __syncthreads();

    const int s = (int)(((long)blockIdx.x * NTILES) / GCTAS);
    const int e = (int)(((long)(blockIdx.x + 1) * NTILES) / GCTAS);

    int aph[2] = {0, 0}, bph = 0;
    int ab = 0;
    bool a_issued = false;
    int prev_bj = -1;
    const half2 SC = __float2half2_rn(2.8853900817779268f);   // 2*log2(e)

    for (int t = s; t < e; t++) {
        int bi, bj;
        tile_decode(t, bi, bj);
        const bool diag = (bi == bj);
        const bool newcol = (bj != prev_bj);
        prev_bj = bj;
        const int iBase = bi * 128;
        const int jBase = bj * 128;

        __syncthreads();

        if (tid == 0) {
            if (newcol) {
                MBAR_EXPECT(sb + SMEM_MBB, 65536u);
                #pragma unroll
                for (int q = 0; q < 8; q++)
                    BULK_LD(sb + SMEM_B + q * 8192,
                            (const char*)&g_normh[(size_t)jBase * D] + q * 8192, 8192u, sb + SMEM_MBB);
            }
            if (!diag && !a_issued) {
                uint32_t mba = sb + (ab ? SMEM_MBA1 : SMEM_MBA0);
                uint32_t abuf = (ab ? SMEM_A1 : SMEM_A0);
                MBAR_EXPECT(mba, 65536u);
                #pragma unroll
                for (int q = 0; q < 8; q++)
                    BULK_LD(sb + abuf + q * 8192,
                            (const char*)&g_normh[(size_t)iBase * D] + q * 8192, 8192u, mba);
            }
        }
        // stage labels for this tile (visible after post-wait sync)
        if (tid < 64) ((unsigned*)(smem + SMEM_LABI))[tid] = ((const unsigned*)&g_labh[iBase])[tid];
        else if (tid < 128) ((unsigned*)(smem + SMEM_LABJ))[tid - 64] = ((const unsigned*)&g_labh[jBase])[tid - 64];

        if (newcol) { mbar_wait(sb + SMEM_MBB, bph); bph ^= 1; }
        if (!diag)  { mbar_wait(sb + (ab ? SMEM_MBA1 : SMEM_MBA0), aph[ab]); aph[ab] ^= 1; }
        __syncthreads();

        float acc[2][4][4];
        #pragma unroll
        for (int mt = 0; mt < 2; mt++)
            #pragma unroll
            for (int nt = 0; nt < 4; nt++)
                #pragma unroll
                for (int ee = 0; ee < 4; ee++) acc[mt][nt][ee] = 0.f;

        const uint32_t aspace = diag ? (uint32_t)SMEM_B : (ab ? (uint32_t)SMEM_A1 : (uint32_t)SMEM_A0);
        const int row_a = wm * 32 + (l & 15);
        const uint32_t abase = sb + aspace + (uint32_t)row_a * 512;
        const int rxa = row_a & 7;
        const int hia = (l >> 4);
        const int row_b = wn * 32 + (l & 7) + ((l & 16) ? 8 : 0);
        const uint32_t bbase = sb + SMEM_B + (uint32_t)row_b * 512;
        const int rxb = row_b & 7;
        const int hib = (l >> 3) & 1;

        #pragma unroll
        for (int ks = 0; ks < 16; ks++) {
            const uint32_t ka = (uint32_t)(((ks * 2 + hia) ^ rxa) << 4);
            const uint32_t kb = (uint32_t)(((ks * 2 + hib) ^ rxb) << 4);
            uint32_t A0[4], A1[4];
            LDSM4(A0, abase + ka);
            LDSM4(A1, abase + 8192 + ka);
            #pragma unroll
            for (int p = 0; p < 2; p++) {
                uint32_t Bt[4];
                LDSM4T(Bt, bbase + (uint32_t)p * 8192 + kb);
                MMA16816(acc[0][2 * p],     A0, Bt[0], Bt[1]);
                MMA16816(acc[0][2 * p + 1], A0, Bt[2], Bt[3]);
                MMA16816(acc[1][2 * p],     A1, Bt[0], Bt[1]);
                MMA16816(acc[1][2 * p + 1], A1, Bt[2], Bt[3]);
            }
        }
        __syncthreads();

        a_issued = false;
        if (t + 1 < e) {
            int bi2, bj2;
            tile_decode(t + 1, bi2, bj2);
            if (bi2 != bj2) {
                const int nb = diag ? ab : (ab ^ 1);
                if (tid == 0) {
                    uint32_t mba = sb + (nb ? SMEM_MBA1 : SMEM_MBA0);
                    uint32_t abuf = (nb ? SMEM_A1 : SMEM_A0);
                    MBAR_EXPECT(mba, 65536u);
                    #pragma unroll
                    for (int q = 0; q < 8; q++)
                        BULK_LD(sb + abuf + q * 8192,
                                (const char*)&g_normh[(size_t)(bi2 * 128) * D] + q * 8192, 8192u, mba);
                }
                ab = nb;
                a_issued = true;
            }
        }

        // ---- epilogue: neg = sum of exp(2s) over label-mismatched cols ----
        half2 cneg2[4];
        #pragma unroll
        for (int nt = 0; nt < 4; nt++) cneg2[nt] = __float2half2_rn(0.f);

        #pragma unroll
        for (int mt = 0; mt < 2; mt++) {
            #pragma unroll
            for (int half_ = 0; half_ < 2; half_++) {
                const int row_local = wm * 32 + mt * 16 + half_ * 8 + (l >> 2);
                const int gi = iBase + row_local;
                const half2 li2 = __half2half2(labih[row_local]);
                half2 t2 = __float2half2_rn(0.f);
                #pragma unroll
                for (int nt = 0; nt < 4; nt++) {
                    half2 h = __floats2half2_rn(acc[mt][nt][half_ * 2], acc[mt][nt][half_ * 2 + 1]);
                    half2 ex = h2exp2(__hmul2(h, SC));
                    half2 m2 = __heq2(labjh2[wn * 16 + nt * 4 + (l & 3)], li2);
                    half2 nx = __hsub2(ex, __hmul2(ex, m2));
                    t2 = __hadd2(t2, nx);
                    cneg2[nt] = __hadd2(cneg2[nt], nx);
                    unsigned mu = *(unsigned*)&m2;
                    if (mu) {
                        const int col0 = jBase + wn * 32 + nt * 8 + (l & 3) * 2;
                        if ((mu & 0xFFFFu) && gi < col0) {
                            unsigned idx = atomicAdd(scnt, 1u);
                            if (idx < PBUF_CAP) { spij[idx] = ((unsigned)gi << 12) | (unsigned)col0; sps[idx] = acc[mt][nt][half_ * 2]; }
                            else { unsigned gp = atomicAdd(&g_npair, 1u); if (gp < PAIR_CAP) { g_pair_ij[gp] = ((unsigned)gi << 12) | (unsigned)col0; g_pair_s[gp] = acc[mt][nt][half_ * 2]; } }
                        }
                        if ((mu >> 16) && gi < col0 + 1) {
                            unsigned idx = atomicAdd(scnt, 1u);
                            if (idx < PBUF_CAP) { spij[idx] = ((unsigned)gi << 12) | (unsigned)(col0 + 1); sps[idx] = acc[mt][nt][half_ * 2 + 1]; }
                            else { unsigned gp = atomicAdd(&g_npair, 1u); if (gp < PAIR_CAP) { g_pair_ij[gp] = ((unsigned)gi << 12) | (unsigned)(col0 + 1); g_pair_s[gp] = acc[mt][nt][half_ * 2 + 1]; } }
                        }
                    }
                }
                float2 f = __half22float2(t2);
                float tt = f.x + f.y;
                tt += __shfl_xor_sync(0xffffffffu, tt, 1);
                tt += __shfl_xor_sync(0xffffffffu, tt, 2);
                if ((l & 3) == 0) atomicAdd(&g_neg[gi], tt);
            }
        }
        if (!diag) {
            #pragma unroll
            for (int nt = 0; nt < 4; nt++) {
                uint32_t v = *(uint32_t*)&cneg2[nt];
                #pragma unroll
                for (int m = 4; m <= 16; m <<= 1) {
                    uint32_t o = __shfl_xor_sync(0xffffffffu, v, m);
                    half2 hv = *(half2*)&v, ho = *(half2*)&o;
                    hv = __hadd2(hv, ho);
                    v = *(uint32_t*)&hv;
                }
                if (l < 4) {
                    float2 fc = __half22float2(*(half2*)&v);
                    int c0 = wn * 32 + nt * 8 + l * 2;
                    atomicAdd(&g_neg[jBase + c0], fc.x);
                    atomicAdd(&g_neg[jBase + c0 + 1], fc.y);
                }
            }
        }

        // ---- flush pair buffer ----
        __syncthreads();
        if (tid == 0) {
            unsigned c = scnt[0];
            if (c > PBUF_CAP) c = PBUF_CAP;
            scnt[1] = atomicAdd(&g_npair, c);
            scnt[2] = c;
        }
        __syncthreads();
        {
            unsigned c = scnt[2], b = scnt[1];
            for (unsigned i = tid; i < c; i += 512) {
                unsigned gp = b + i;
                if (gp < PAIR_CAP) {
                    g_pair_ij[gp] = spij[i];
                    g_pair_s[gp]  = sps[i];
                }
            }
        }
        if (tid == 0) scnt[0] = 0;
    }
}

// Streaming loss over (i,j,s) records; last block finalizes.
__global__ __launch_bounds__(256) void k_loss(float* __restrict__ out) {
    unsigned np = g_npair;
    if (np > PAIR_CAP) np = PAIR_CAP;
    float lsum = 0.f;
    for (unsigned p = blockIdx.x * 256 + threadIdx.x; p < np; p += gridDim.x * 256) {
        unsigned ij = g_pair_ij[p];
        int i = (int)(ij >> 12);
        int j = (int)(ij & 0xfffu);
        float s = g_pair_s[p];
        float e = __expf(2.0f * s);
        lsum += logf(e + g_neg[i]) + logf(e + g_neg[j]) - 4.0f * s;
    }
    #pragma unroll
    for (int o = 16; o > 0; o >>= 1) lsum += __shfl_down_sync(0xffffffffu, lsum, o);
    __shared__ float sd[8];
    if ((threadIdx.x & 31) == 0) sd[threadIdx.x >> 5] = lsum;
    __syncthreads();
    if (threadIdx.x == 0) {
        float L = sd[0] + sd[1] + sd[2] + sd[3] + sd[4] + sd[5] + sd[6] + sd[7];
        if (L != 0.f) atomicAdd(&g_loss_f, L);
        __threadfence();
        unsigned d = atomicAdd(&g_done, 1u);
        if (d == gridDim.x - 1) {
            float total = atomicAdd(&g_loss_f, 0.f);
            out[0] = np ? (total / (float)(2u * np)) : 0.f;
        }
    }
}

// ---------------- launch ----------------
extern "C" void kernel_launch(void* const* d_in, const int* in_sizes, int n_in,
                              void* d_out, int out_size) {
    const float* x = (const float*)d_in[0];
    const void* labels = d_in[1];

    static bool attr_done = false;
    if (!attr_done) {
        cudaFuncSetAttribute(k_gemm, cudaFuncAttributeMaxDynamicSharedMemorySize, SMEM_GT);
        attr_done = true;
    }

    k_norm<<<256, 256>>>(x, labels);
    k_gemm<<<GCTAS, 512, SMEM_GT>>>();
    k_loss<<<128, 256>>>((float*)d_out);
}